// round 1
// baseline (speedup 1.0000x reference)
#include <cuda_runtime.h>
#include <cstdint>

#define D 64
#define CAP (160000 * D)

// Scratch node-feature buffers (allocation-free rule: __device__ globals).
__device__ float g_x[CAP];
__device__ float g_y[CAP];
__device__ float g_acc[CAP];

// ---------------------------------------------------------------------------
// init: x = concat(user_emb, item_emb); acc = x; y = 0
// ---------------------------------------------------------------------------
__global__ void init_kernel(const float* __restrict__ ue, const float* __restrict__ ie,
                            float* __restrict__ x, float* __restrict__ acc,
                            float* __restrict__ y, int nu_elems, int total_elems) {
    int i = (blockIdx.x * blockDim.x + threadIdx.x) * 4;
    if (i >= total_elems) return;
    float4 v = (i < nu_elems) ? *(const float4*)(ue + i)
                              : *(const float4*)(ie + (i - nu_elems));
    *(float4*)(x + i)   = v;
    *(float4*)(acc + i) = v;
    *(float4*)(y + i)   = make_float4(0.f, 0.f, 0.f, 0.f);
}

// ---------------------------------------------------------------------------
// SPMM: y[dst] += val * x[src].  16 threads per edge, float4 per thread,
// vectorized reduction (red.global.add.v4.f32, sm_90+).
// ---------------------------------------------------------------------------
__global__ void spmm_kernel(const float* __restrict__ x, float* __restrict__ y,
                            const float* __restrict__ ev, const int* __restrict__ es,
                            const int* __restrict__ ed, int nnz) {
    long long idx = (long long)blockIdx.x * blockDim.x + threadIdx.x;
    int e = (int)(idx >> 4);
    if (e >= nnz) return;
    int c = ((int)idx & 15) << 2;

    float v = __ldg(ev + e);
    int   s = __ldg(es + e);
    int   d = __ldg(ed + e);

    const float4 xv = *(const float4*)(x + (size_t)s * D + c);
    float m0 = v * xv.x, m1 = v * xv.y, m2 = v * xv.z, m3 = v * xv.w;
    float* p = y + (size_t)d * D + c;
    asm volatile("red.global.add.v4.f32 [%0], {%1, %2, %3, %4};"
                 :: "l"(p), "f"(m0), "f"(m1), "f"(m2), "f"(m3) : "memory");
}

// ---------------------------------------------------------------------------
// fuse: acc += ynew; zero the old buffer (which becomes next layer's target)
// ---------------------------------------------------------------------------
__global__ void fuse_kernel(float* __restrict__ acc, const float* __restrict__ ynew,
                            float* __restrict__ xold, int total_elems) {
    int i = (blockIdx.x * blockDim.x + threadIdx.x) * 4;
    if (i >= total_elems) return;
    float4 a = *(float4*)(acc + i);
    float4 yv = *(const float4*)(ynew + i);
    a.x += yv.x; a.y += yv.y; a.z += yv.z; a.w += yv.w;
    *(float4*)(acc + i)  = a;
    *(float4*)(xold + i) = make_float4(0.f, 0.f, 0.f, 0.f);
}

// ---------------------------------------------------------------------------
// GEMM: out[b, j] = (acc[users[b]] . acc[nu + j]) / 16
// 128x128 tile, K=64 fully in smem (K-major), 8x8 register tile / thread.
// ---------------------------------------------------------------------------
#define BM 128
#define BN 128
#define LDA 132
#define LDB 132
#define GEMM_SMEM (2 * 64 * 132 * 4)

__global__ void __launch_bounds__(256)
gemm_kernel(const float* __restrict__ acc, const int* __restrict__ users,
            float* __restrict__ out, int batch, int n_items, int n_users) {
    extern __shared__ float smem[];
    float* As = smem;                // [64][LDA]  K-major
    float* Bs = smem + 64 * LDA;     // [64][LDB]  K-major
    __shared__ int urow[BM];

    int tid = threadIdx.x;
    int bm = blockIdx.y, bn = blockIdx.x;

    if (tid < BM) {
        int b = bm * BM + tid;
        urow[tid] = (b < batch) ? users[b] : 0;
    }
    __syncthreads();

    // Load gathered A tile: 128 rows x 16 float4
    #pragma unroll
    for (int l = tid; l < BM * 16; l += 256) {
        int r = l >> 4, kv = (l & 15) << 2;
        float4 v = *(const float4*)(acc + (size_t)urow[r] * D + kv);
        As[(kv + 0) * LDA + r] = v.x;
        As[(kv + 1) * LDA + r] = v.y;
        As[(kv + 2) * LDA + r] = v.z;
        As[(kv + 3) * LDA + r] = v.w;
    }
    // Load B tile (items): 128 rows x 16 float4, guard tail
    #pragma unroll
    for (int l = tid; l < BN * 16; l += 256) {
        int r = l >> 4, kv = (l & 15) << 2;
        int j = bn * BN + r;
        float4 v = make_float4(0.f, 0.f, 0.f, 0.f);
        if (j < n_items) v = *(const float4*)(acc + (size_t)(n_users + j) * D + kv);
        Bs[(kv + 0) * LDB + r] = v.x;
        Bs[(kv + 1) * LDB + r] = v.y;
        Bs[(kv + 2) * LDB + r] = v.z;
        Bs[(kv + 3) * LDB + r] = v.w;
    }
    __syncthreads();

    int ty = tid >> 4;   // m group (0..15)
    int tx = tid & 15;   // n group (0..15)

    float accv[8][8];
    #pragma unroll
    for (int i = 0; i < 8; i++)
        #pragma unroll
        for (int j = 0; j < 8; j++) accv[i][j] = 0.f;

    #pragma unroll 4
    for (int k = 0; k < 64; k++) {
        float4 a0 = *(float4*)&As[k * LDA + ty * 8];
        float4 a1 = *(float4*)&As[k * LDA + ty * 8 + 4];
        float4 b0 = *(float4*)&Bs[k * LDB + tx * 8];
        float4 b1 = *(float4*)&Bs[k * LDB + tx * 8 + 4];
        float a[8] = {a0.x, a0.y, a0.z, a0.w, a1.x, a1.y, a1.z, a1.w};
        float b[8] = {b0.x, b0.y, b0.z, b0.w, b1.x, b1.y, b1.z, b1.w};
        #pragma unroll
        for (int i = 0; i < 8; i++)
            #pragma unroll
            for (int j = 0; j < 8; j++) accv[i][j] += a[i] * b[j];
    }

    const float S = 0.0625f;  // (1/4)*(1/4)
    #pragma unroll
    for (int i = 0; i < 8; i++) {
        int m = bm * BM + ty * 8 + i;
        if (m >= batch) continue;
        #pragma unroll
        for (int j = 0; j < 8; j += 4) {
            int n = bn * BN + tx * 8 + j;
            if (n + 3 < n_items) {
                float4 o = make_float4(accv[i][j] * S, accv[i][j + 1] * S,
                                       accv[i][j + 2] * S, accv[i][j + 3] * S);
                *(float4*)(out + (size_t)m * n_items + n) = o;
            } else {
                for (int q = 0; q < 4; q++)
                    if (n + q < n_items)
                        out[(size_t)m * n_items + n + q] = accv[i][j + q] * S;
            }
        }
    }
}

// ---------------------------------------------------------------------------
extern "C" void kernel_launch(void* const* d_in, const int* in_sizes, int n_in,
                              void* d_out, int out_size) {
    const float* ue    = (const float*)d_in[0];
    const float* ie    = (const float*)d_in[1];
    const float* ev    = (const float*)d_in[2];
    const int*   es    = (const int*)d_in[3];
    const int*   ed    = (const int*)d_in[4];
    const int*   users = (const int*)d_in[5];

    int nu    = in_sizes[0] / D;
    int ni    = in_sizes[1] / D;
    int nnz   = in_sizes[2];
    int batch = in_sizes[5];
    int total = (nu + ni) * D;

    float *x, *y, *acc;
    cudaGetSymbolAddress((void**)&x,   g_x);
    cudaGetSymbolAddress((void**)&y,   g_y);
    cudaGetSymbolAddress((void**)&acc, g_acc);

    int ew_blocks = (total / 4 + 255) / 256;
    init_kernel<<<ew_blocks, 256>>>(ue, ie, x, acc, y, nu * D, total);

    float* cur = x;
    float* nxt = y;
    for (int l = 0; l < 3; l++) {
        long long t = (long long)nnz * 16;
        int blocks = (int)((t + 255) / 256);
        spmm_kernel<<<blocks, 256>>>(cur, nxt, ev, es, ed, nnz);
        fuse_kernel<<<ew_blocks, 256>>>(acc, nxt, cur, total);
        float* tmp = cur; cur = nxt; nxt = tmp;
    }

    cudaFuncSetAttribute(gemm_kernel, cudaFuncAttributeMaxDynamicSharedMemorySize,
                         GEMM_SMEM);
    dim3 grid((ni + BN - 1) / BN, (batch + BM - 1) / BM);
    gemm_kernel<<<grid, 256, GEMM_SMEM>>>(acc, users, (float*)d_out, batch, ni, nu);
}

// round 2
// speedup vs baseline: 1.4224x; 1.4224x over previous
#include <cuda_runtime.h>
#include <cstdint>

#define D 64
#define NCAP 160000
#define ECAP 4200000

// Scratch (allocation-free rule: __device__ globals).
__device__ float g_x[NCAP * D];
__device__ float g_y[NCAP * D];
__device__ float g_acc[NCAP * D];
__device__ int   g_cnt[NCAP];       // per-dst degree
__device__ int   g_off[NCAP];       // exclusive prefix (CSR row start)
__device__ int   g_cur[NCAP];       // scatter cursors
__device__ int   g_bsum[1024];      // block sums for scan
__device__ float g_eval[ECAP];      // dst-sorted edge values
__device__ int   g_esrc[ECAP];      // dst-sorted edge sources

// ---------------------------------------------------------------------------
__global__ void zero_cnt_kernel(int* __restrict__ cnt, int n) {
    int i = blockIdx.x * blockDim.x + threadIdx.x;
    if (i < n) cnt[i] = 0;
}

// init: x = concat(user_emb, item_emb); acc = x
__global__ void init_kernel(const float* __restrict__ ue, const float* __restrict__ ie,
                            float* __restrict__ x, float* __restrict__ acc,
                            int nu_elems, int total_elems) {
    int i = (blockIdx.x * blockDim.x + threadIdx.x) * 4;
    if (i >= total_elems) return;
    float4 v = (i < nu_elems) ? *(const float4*)(ue + i)
                              : *(const float4*)(ie + (i - nu_elems));
    *(float4*)(x + i)   = v;
    *(float4*)(acc + i) = v;
}

// ---------------------------------------------------------------------------
// CSR build: histogram -> 3-kernel scan -> scatter
// ---------------------------------------------------------------------------
__global__ void hist_kernel(const int* __restrict__ ed, int* __restrict__ cnt, int nnz) {
    int e = blockIdx.x * blockDim.x + threadIdx.x;
    if (e < nnz) atomicAdd(&cnt[ed[e]], 1);
}

// Per-1024 block exclusive scan; block totals to bsum.
__global__ void scan_blocks_kernel(const int* __restrict__ cnt, int* __restrict__ off,
                                   int* __restrict__ bsum, int n) {
    __shared__ int s[1024];
    int tid = threadIdx.x;
    int gid = blockIdx.x * 1024 + tid;
    int v = (gid < n) ? cnt[gid] : 0;
    s[tid] = v;
    __syncthreads();
    #pragma unroll
    for (int o = 1; o < 1024; o <<= 1) {
        int t = (tid >= o) ? s[tid - o] : 0;
        __syncthreads();
        s[tid] += t;
        __syncthreads();
    }
    if (gid < n) off[gid] = s[tid] - v;            // exclusive
    if (tid == 1023) bsum[blockIdx.x] = s[1023];   // inclusive total
}

// Single-block exclusive scan of block sums (nb <= 1024).
__global__ void scan_bsum_kernel(int* __restrict__ bsum, int nb) {
    __shared__ int s[1024];
    int tid = threadIdx.x;
    int v = (tid < nb) ? bsum[tid] : 0;
    s[tid] = v;
    __syncthreads();
    #pragma unroll
    for (int o = 1; o < 1024; o <<= 1) {
        int t = (tid >= o) ? s[tid - o] : 0;
        __syncthreads();
        s[tid] += t;
        __syncthreads();
    }
    if (tid < nb) bsum[tid] = s[tid] - v;
}

__global__ void scan_add_kernel(int* __restrict__ off, int* __restrict__ cur,
                                const int* __restrict__ bsum, int n) {
    int gid = blockIdx.x * blockDim.x + threadIdx.x;
    if (gid < n) {
        int o = off[gid] + bsum[gid >> 10];
        off[gid] = o;
        cur[gid] = o;
    }
}

__global__ void scatter_kernel(const float* __restrict__ ev, const int* __restrict__ es,
                               const int* __restrict__ ed, int* __restrict__ cur,
                               float* __restrict__ oval, int* __restrict__ osrc, int nnz) {
    int e = blockIdx.x * blockDim.x + threadIdx.x;
    if (e < nnz) {
        int d = ed[e];
        int p = atomicAdd(&cur[d], 1);
        oval[p] = ev[e];
        osrc[p] = es[e];
    }
}

// ---------------------------------------------------------------------------
// CSR SPMM, one warp per node, atomic-free.
//   y[n] = sum_{e in CSR[n]} val[e] * x[src[e]];  acc[n] += y[n]
// Metadata read coalesced in 32-edge chunks, shfl-broadcast to the warp.
// Each lane owns 2 feature columns (float2).
// ---------------------------------------------------------------------------
__global__ void __launch_bounds__(256)
spmm_csr_kernel(const float* __restrict__ x, float* __restrict__ y,
                float* __restrict__ accb,
                const int* __restrict__ off, const int* __restrict__ cnt,
                const float* __restrict__ eval, const int* __restrict__ esrc,
                int n_nodes) {
    int warp = (blockIdx.x * blockDim.x + threadIdx.x) >> 5;
    int lane = threadIdx.x & 31;
    if (warp >= n_nodes) return;

    int start = __ldg(off + warp);
    int deg   = __ldg(cnt + warp);

    float a0 = 0.f, a1 = 0.f;
    for (int base = 0; base < deg; base += 32) {
        int m = deg - base;
        if (m > 32) m = 32;
        float evv = 0.f;
        int   esv = 0;
        if (lane < m) {
            evv = __ldg(eval + start + base + lane);
            esv = __ldg(esrc + start + base + lane);
        }
        #pragma unroll 4
        for (int t = 0; t < m; t++) {
            float v = __shfl_sync(0xffffffff, evv, t);
            int   s = __shfl_sync(0xffffffff, esv, t);
            float2 xv = *(const float2*)(x + (size_t)s * D + lane * 2);
            a0 += v * xv.x;
            a1 += v * xv.y;
        }
    }

    size_t o = (size_t)warp * D + lane * 2;
    *(float2*)(y + o) = make_float2(a0, a1);
    float2 ac = *(float2*)(accb + o);
    ac.x += a0;
    ac.y += a1;
    *(float2*)(accb + o) = ac;
}

// ---------------------------------------------------------------------------
// GEMM: out[b, j] = (acc[users[b]] . acc[nu + j]) / 16
// ---------------------------------------------------------------------------
#define BM 128
#define BN 128
#define LDA 132
#define LDB 132
#define GEMM_SMEM (2 * 64 * 132 * 4)

__global__ void __launch_bounds__(256)
gemm_kernel(const float* __restrict__ acc, const int* __restrict__ users,
            float* __restrict__ out, int batch, int n_items, int n_users) {
    extern __shared__ float smem[];
    float* As = smem;
    float* Bs = smem + 64 * LDA;
    __shared__ int urow[BM];

    int tid = threadIdx.x;
    int bm = blockIdx.y, bn = blockIdx.x;

    if (tid < BM) {
        int b = bm * BM + tid;
        urow[tid] = (b < batch) ? users[b] : 0;
    }
    __syncthreads();

    #pragma unroll
    for (int l = tid; l < BM * 16; l += 256) {
        int r = l >> 4, kv = (l & 15) << 2;
        float4 v = *(const float4*)(acc + (size_t)urow[r] * D + kv);
        As[(kv + 0) * LDA + r] = v.x;
        As[(kv + 1) * LDA + r] = v.y;
        As[(kv + 2) * LDA + r] = v.z;
        As[(kv + 3) * LDA + r] = v.w;
    }
    #pragma unroll
    for (int l = tid; l < BN * 16; l += 256) {
        int r = l >> 4, kv = (l & 15) << 2;
        int j = bn * BN + r;
        float4 v = make_float4(0.f, 0.f, 0.f, 0.f);
        if (j < n_items) v = *(const float4*)(acc + (size_t)(n_users + j) * D + kv);
        Bs[(kv + 0) * LDB + r] = v.x;
        Bs[(kv + 1) * LDB + r] = v.y;
        Bs[(kv + 2) * LDB + r] = v.z;
        Bs[(kv + 3) * LDB + r] = v.w;
    }
    __syncthreads();

    int ty = tid >> 4;
    int tx = tid & 15;

    float accv[8][8];
    #pragma unroll
    for (int i = 0; i < 8; i++)
        #pragma unroll
        for (int j = 0; j < 8; j++) accv[i][j] = 0.f;

    #pragma unroll 4
    for (int k = 0; k < 64; k++) {
        float4 a0 = *(float4*)&As[k * LDA + ty * 8];
        float4 a1 = *(float4*)&As[k * LDA + ty * 8 + 4];
        float4 b0 = *(float4*)&Bs[k * LDB + tx * 8];
        float4 b1 = *(float4*)&Bs[k * LDB + tx * 8 + 4];
        float a[8] = {a0.x, a0.y, a0.z, a0.w, a1.x, a1.y, a1.z, a1.w};
        float b[8] = {b0.x, b0.y, b0.z, b0.w, b1.x, b1.y, b1.z, b1.w};
        #pragma unroll
        for (int i = 0; i < 8; i++)
            #pragma unroll
            for (int j = 0; j < 8; j++) accv[i][j] += a[i] * b[j];
    }

    const float S = 0.0625f;
    #pragma unroll
    for (int i = 0; i < 8; i++) {
        int m = bm * BM + ty * 8 + i;
        if (m >= batch) continue;
        #pragma unroll
        for (int j = 0; j < 8; j += 4) {
            int n = bn * BN + tx * 8 + j;
            if (n + 3 < n_items) {
                float4 o = make_float4(accv[i][j] * S, accv[i][j + 1] * S,
                                       accv[i][j + 2] * S, accv[i][j + 3] * S);
                *(float4*)(out + (size_t)m * n_items + n) = o;
            } else {
                for (int q = 0; q < 4; q++)
                    if (n + q < n_items)
                        out[(size_t)m * n_items + n + q] = accv[i][j + q] * S;
            }
        }
    }
}

// ---------------------------------------------------------------------------
extern "C" void kernel_launch(void* const* d_in, const int* in_sizes, int n_in,
                              void* d_out, int out_size) {
    const float* ue    = (const float*)d_in[0];
    const float* ie    = (const float*)d_in[1];
    const float* ev    = (const float*)d_in[2];
    const int*   es    = (const int*)d_in[3];
    const int*   ed    = (const int*)d_in[4];
    const int*   users = (const int*)d_in[5];

    int nu    = in_sizes[0] / D;
    int ni    = in_sizes[1] / D;
    int nnz   = in_sizes[2];
    int batch = in_sizes[5];
    int n_nodes = nu + ni;
    int total = n_nodes * D;

    float *x, *y, *acc, *eval;
    int *cnt, *off, *cur, *bsum, *esrc;
    cudaGetSymbolAddress((void**)&x,    g_x);
    cudaGetSymbolAddress((void**)&y,    g_y);
    cudaGetSymbolAddress((void**)&acc,  g_acc);
    cudaGetSymbolAddress((void**)&cnt,  g_cnt);
    cudaGetSymbolAddress((void**)&off,  g_off);
    cudaGetSymbolAddress((void**)&cur,  g_cur);
    cudaGetSymbolAddress((void**)&bsum, g_bsum);
    cudaGetSymbolAddress((void**)&eval, g_eval);
    cudaGetSymbolAddress((void**)&esrc, g_esrc);

    // --- init + CSR build ---
    zero_cnt_kernel<<<(n_nodes + 255) / 256, 256>>>(cnt, n_nodes);
    init_kernel<<<(total / 4 + 255) / 256, 256>>>(ue, ie, x, acc, nu * D, total);
    hist_kernel<<<(nnz + 255) / 256, 256>>>(ed, cnt, nnz);

    int nb = (n_nodes + 1023) / 1024;
    scan_blocks_kernel<<<nb, 1024>>>(cnt, off, bsum, n_nodes);
    scan_bsum_kernel<<<1, 1024>>>(bsum, nb);
    scan_add_kernel<<<(n_nodes + 255) / 256, 256>>>(off, cur, bsum, n_nodes);
    scatter_kernel<<<(nnz + 255) / 256, 256>>>(ev, es, ed, cur, eval, esrc, nnz);

    // --- 3 propagation layers (fused acc update) ---
    float* curx = x;
    float* nxt  = y;
    for (int l = 0; l < 3; l++) {
        long long t = (long long)n_nodes * 32;
        int blocks = (int)((t + 255) / 256);
        spmm_csr_kernel<<<blocks, 256>>>(curx, nxt, acc, off, cnt, eval, esrc, n_nodes);
        float* tmp = curx; curx = nxt; nxt = tmp;
    }

    // --- rating GEMM ---
    cudaFuncSetAttribute(gemm_kernel, cudaFuncAttributeMaxDynamicSharedMemorySize,
                         GEMM_SMEM);
    dim3 grid((ni + BN - 1) / BN, (batch + BM - 1) / BM);
    gemm_kernel<<<grid, 256, GEMM_SMEM>>>(acc, users, (float*)d_out, batch, ni, nu);
}

// round 4
// speedup vs baseline: 1.8920x; 1.3301x over previous
#include <cuda_runtime.h>
#include <cuda_bf16.h>
#include <cstdint>

#define D 64
#define NCAP 160000
#define ECAP 4200000
#define GK 192            // split-K: A'=[hi,hi,lo], B'=[hi,lo,hi]
#define APCAP (4096 * GK)
#define BPCAP (51200 * GK)

// Scratch (allocation-free rule: __device__ globals).
__device__ float g_x[NCAP * D];
__device__ float g_y[NCAP * D];
__device__ float g_acc[NCAP * D];
__device__ int   g_cnt[NCAP];
__device__ int   g_off[NCAP];
__device__ int   g_cur[NCAP];
__device__ int   g_bsum[1024];
__device__ float g_eval[ECAP];
__device__ int   g_esrc[ECAP];
__device__ __nv_bfloat16 g_Ap[APCAP];   // split A' [batch, GK]
__device__ __nv_bfloat16 g_Bp[BPCAP];   // split B' [ni_pad, GK]

// ---------------------------------------------------------------------------
__global__ void zero_cnt_kernel(int* __restrict__ cnt, int n) {
    int i = blockIdx.x * blockDim.x + threadIdx.x;
    if (i < n) cnt[i] = 0;
}

__global__ void init_kernel(const float* __restrict__ ue, const float* __restrict__ ie,
                            float* __restrict__ x, float* __restrict__ acc,
                            int nu_elems, int total_elems) {
    int i = (blockIdx.x * blockDim.x + threadIdx.x) * 4;
    if (i >= total_elems) return;
    float4 v = (i < nu_elems) ? *(const float4*)(ue + i)
                              : *(const float4*)(ie + (i - nu_elems));
    *(float4*)(x + i)   = v;
    *(float4*)(acc + i) = v;
}

// ---------------------------------------------------------------------------
// CSR build: histogram -> 3-kernel scan -> scatter
// ---------------------------------------------------------------------------
__global__ void hist_kernel(const int* __restrict__ ed, int* __restrict__ cnt, int nnz) {
    int e = blockIdx.x * blockDim.x + threadIdx.x;
    if (e < nnz) atomicAdd(&cnt[ed[e]], 1);
}

__global__ void scan_blocks_kernel(const int* __restrict__ cnt, int* __restrict__ off,
                                   int* __restrict__ bsum, int n) {
    __shared__ int s[1024];
    int tid = threadIdx.x;
    int gid = blockIdx.x * 1024 + tid;
    int v = (gid < n) ? cnt[gid] : 0;
    s[tid] = v;
    __syncthreads();
    #pragma unroll
    for (int o = 1; o < 1024; o <<= 1) {
        int t = (tid >= o) ? s[tid - o] : 0;
        __syncthreads();
        s[tid] += t;
        __syncthreads();
    }
    if (gid < n) off[gid] = s[tid] - v;
    if (tid == 1023) bsum[blockIdx.x] = s[1023];
}

__global__ void scan_bsum_kernel(int* __restrict__ bsum, int nb) {
    __shared__ int s[1024];
    int tid = threadIdx.x;
    int v = (tid < nb) ? bsum[tid] : 0;
    s[tid] = v;
    __syncthreads();
    #pragma unroll
    for (int o = 1; o < 1024; o <<= 1) {
        int t = (tid >= o) ? s[tid - o] : 0;
        __syncthreads();
        s[tid] += t;
        __syncthreads();
    }
    if (tid < nb) bsum[tid] = s[tid] - v;
}

__global__ void scan_add_kernel(int* __restrict__ off, int* __restrict__ cur,
                                const int* __restrict__ bsum, int n) {
    int gid = blockIdx.x * blockDim.x + threadIdx.x;
    if (gid < n) {
        int o = off[gid] + bsum[gid >> 10];
        off[gid] = o;
        cur[gid] = o;
    }
}

__global__ void scatter_kernel(const float* __restrict__ ev, const int* __restrict__ es,
                               const int* __restrict__ ed, int* __restrict__ cur,
                               float* __restrict__ oval, int* __restrict__ osrc, int nnz) {
    int e = blockIdx.x * blockDim.x + threadIdx.x;
    if (e < nnz) {
        int d = ed[e];
        int p = atomicAdd(&cur[d], 1);
        oval[p] = ev[e];
        osrc[p] = es[e];
    }
}

// ---------------------------------------------------------------------------
// CSR SPMM, one warp per node, atomic-free, acc fused.
// ---------------------------------------------------------------------------
__global__ void __launch_bounds__(256)
spmm_csr_kernel(const float* __restrict__ x, float* __restrict__ y,
                float* __restrict__ accb,
                const int* __restrict__ off, const int* __restrict__ cnt,
                const float* __restrict__ eval, const int* __restrict__ esrc,
                int n_nodes) {
    int warp = (blockIdx.x * blockDim.x + threadIdx.x) >> 5;
    int lane = threadIdx.x & 31;
    if (warp >= n_nodes) return;

    int start = __ldg(off + warp);
    int deg   = __ldg(cnt + warp);

    float a0 = 0.f, a1 = 0.f;
    for (int base = 0; base < deg; base += 32) {
        int m = deg - base;
        if (m > 32) m = 32;
        float evv = 0.f;
        int   esv = 0;
        if (lane < m) {
            evv = __ldg(eval + start + base + lane);
            esv = __ldg(esrc + start + base + lane);
        }
        #pragma unroll 4
        for (int t = 0; t < m; t++) {
            float v = __shfl_sync(0xffffffff, evv, t);
            int   s = __shfl_sync(0xffffffff, esv, t);
            float2 xv = *(const float2*)(x + (size_t)s * D + lane * 2);
            a0 += v * xv.x;
            a1 += v * xv.y;
        }
    }

    size_t o = (size_t)warp * D + lane * 2;
    *(float2*)(y + o) = make_float2(a0, a1);
    float2 ac = *(float2*)(accb + o);
    ac.x += a0;
    ac.y += a1;
    *(float2*)(accb + o) = ac;
}

// ---------------------------------------------------------------------------
// Split-precision conversion:  v = hi(bf16) + lo(bf16) + O(2^-16 v)
// ---------------------------------------------------------------------------
__device__ __forceinline__ void split2(float a0, float a1,
                                       __nv_bfloat162* hi, __nv_bfloat162* lo) {
    __nv_bfloat16 h0 = __float2bfloat16_rn(a0);
    __nv_bfloat16 h1 = __float2bfloat16_rn(a1);
    __nv_bfloat16 l0 = __float2bfloat16_rn(a0 - __bfloat162float(h0));
    __nv_bfloat16 l1 = __float2bfloat16_rn(a1 - __bfloat162float(h1));
    *hi = __nv_bfloat162(h0, h1);
    *lo = __nv_bfloat162(l0, l1);
}

__global__ void buildA_kernel(const float* __restrict__ acc, const int* __restrict__ users,
                              __nv_bfloat16* __restrict__ Ap, int batch) {
    int idx = blockIdx.x * blockDim.x + threadIdx.x;
    int total = batch * (GK / 2);
    if (idx >= total) return;
    int b = idx / (GK / 2), c2 = idx % (GK / 2);
    int sec = (c2 * 2) / D, k = (c2 * 2) % D;
    int u = __ldg(users + b);
    float2 v = *(const float2*)(acc + (size_t)u * D + k);
    __nv_bfloat162 hi, lo;
    split2(v.x, v.y, &hi, &lo);
    *(__nv_bfloat162*)(Ap + (size_t)b * GK + c2 * 2) = (sec == 2) ? lo : hi;
}

__global__ void buildB_kernel(const float* __restrict__ acc, __nv_bfloat16* __restrict__ Bp,
                              int nu, int ni, int nipad) {
    int idx = blockIdx.x * blockDim.x + threadIdx.x;
    int total = nipad * (GK / 2);
    if (idx >= total) return;
    int j = idx / (GK / 2), c2 = idx % (GK / 2);
    int sec = (c2 * 2) / D, k = (c2 * 2) % D;
    float2 v = make_float2(0.f, 0.f);
    if (j < ni) v = *(const float2*)(acc + (size_t)(nu + j) * D + k);
    __nv_bfloat162 hi, lo;
    split2(v.x, v.y, &hi, &lo);
    *(__nv_bfloat162*)(Bp + (size_t)j * GK + c2 * 2) = (sec == 1) ? lo : hi;
}

// ---------------------------------------------------------------------------
// HMMA GEMM (compute_103-safe: ldmatrix + mma.sync.m16n8k16 bf16):
//   out[128 x 128] tile = A'[128,192] . B'[128,192]^T * (1/16)
// 8 warps: 2(m) x 4(n), each warp 64x32 = 4x4 tiles of m16n8.
// SMEM rows padded to 400B -> ldmatrix conflict-free (row stride = 4 banks).
// ---------------------------------------------------------------------------
#define ROWB 400
#define BOFF (128 * ROWB)
#define GEMM_SMEM_TOT (2 * 128 * ROWB)   // 102400

__device__ __forceinline__ uint32_t smem_u32(const void* p) {
    uint32_t a;
    asm("{ .reg .u64 t; cvta.to.shared.u64 t, %1; cvt.u32.u64 %0, t; }"
        : "=r"(a) : "l"(p));
    return a;
}

__global__ void __launch_bounds__(256)
gemm_mma_kernel(const __nv_bfloat16* __restrict__ Ap, const __nv_bfloat16* __restrict__ Bp,
                float* __restrict__ out, int batch, int n_items) {
    extern __shared__ char smem[];
    uint32_t sbase = smem_u32(smem);
    int tid = threadIdx.x;
    int wid = tid >> 5;
    int lane = tid & 31;
    int bm = blockIdx.y, bn = blockIdx.x;

    // Fill A/B tiles: 128 rows x 24 16B-chunks each.
    const char* Agp = (const char*)(Ap + (size_t)bm * 128 * GK);
    const char* Bgp = (const char*)(Bp + (size_t)bn * 128 * GK);
    #pragma unroll 4
    for (int i = tid; i < 128 * 24; i += 256) {
        int r = i / 24, c = i % 24;
        *(uint4*)(smem + r * ROWB + c * 16)        = *(const uint4*)(Agp + r * 384 + c * 16);
        *(uint4*)(smem + BOFF + r * ROWB + c * 16) = *(const uint4*)(Bgp + r * 384 + c * 16);
    }
    __syncthreads();

    int wm = (wid >> 2) * 64;   // warp m offset
    int wn = (wid & 3) * 32;    // warp n offset

    float c[4][4][4];
    #pragma unroll
    for (int mt = 0; mt < 4; mt++)
        #pragma unroll
        for (int nt = 0; nt < 4; nt++)
            #pragma unroll
            for (int q = 0; q < 4; q++) c[mt][nt][q] = 0.f;

    // lane-invariant address parts
    uint32_t a_row = wm + (lane & 15);
    uint32_t a_kb  = (lane & 16) ? 16u : 0u;     // k-half, bytes
    uint32_t b_row = wn + (lane & 7);
    uint32_t b_kb  = (lane & 8) ? 16u : 0u;

    #pragma unroll
    for (int ks = 0; ks < 12; ks++) {
        uint32_t kb = ks * 32;                   // 16 bf16 = 32B per step
        uint32_t a[4][4], b[4][2];
        #pragma unroll
        for (int mt = 0; mt < 4; mt++) {
            uint32_t addr = sbase + (a_row + mt * 16) * ROWB + kb + a_kb;
            asm volatile("ldmatrix.sync.aligned.m8n8.x4.shared.b16 {%0,%1,%2,%3}, [%4];"
                         : "=r"(a[mt][0]), "=r"(a[mt][1]), "=r"(a[mt][2]), "=r"(a[mt][3])
                         : "r"(addr));
        }
        #pragma unroll
        for (int nt = 0; nt < 4; nt++) {
            uint32_t addr = sbase + BOFF + (b_row + nt * 8) * ROWB + kb + b_kb;
            asm volatile("ldmatrix.sync.aligned.m8n8.x2.shared.b16 {%0,%1}, [%2];"
                         : "=r"(b[nt][0]), "=r"(b[nt][1])
                         : "r"(addr));
        }
        #pragma unroll
        for (int mt = 0; mt < 4; mt++)
            #pragma unroll
            for (int nt = 0; nt < 4; nt++) {
                asm volatile(
                    "mma.sync.aligned.m16n8k16.row.col.f32.bf16.bf16.f32 "
                    "{%0,%1,%2,%3}, {%4,%5,%6,%7}, {%8,%9}, {%0,%1,%2,%3};"
                    : "+f"(c[mt][nt][0]), "+f"(c[mt][nt][1]),
                      "+f"(c[mt][nt][2]), "+f"(c[mt][nt][3])
                    : "r"(a[mt][0]), "r"(a[mt][1]), "r"(a[mt][2]), "r"(a[mt][3]),
                      "r"(b[nt][0]), "r"(b[nt][1]));
            }
    }

    // Epilogue: direct global stores.
    const float S = 0.0625f;
    int gr = lane >> 2;          // group row 0..7
    int gc = (lane & 3) * 2;     // col pair
    #pragma unroll
    for (int mt = 0; mt < 4; mt++) {
        int m0 = bm * 128 + wm + mt * 16 + gr;
        int m1 = m0 + 8;
        #pragma unroll
        for (int nt = 0; nt < 4; nt++) {
            int n = bn * 128 + wn + nt * 8 + gc;
            if (n < n_items) {
                if (m0 < batch)
                    *(float2*)(out + (size_t)m0 * n_items + n) =
                        make_float2(c[mt][nt][0] * S, c[mt][nt][1] * S);
                if (m1 < batch)
                    *(float2*)(out + (size_t)m1 * n_items + n) =
                        make_float2(c[mt][nt][2] * S, c[mt][nt][3] * S);
            }
        }
    }
}

// ---------------------------------------------------------------------------
extern "C" void kernel_launch(void* const* d_in, const int* in_sizes, int n_in,
                              void* d_out, int out_size) {
    const float* ue    = (const float*)d_in[0];
    const float* ie    = (const float*)d_in[1];
    const float* ev    = (const float*)d_in[2];
    const int*   es    = (const int*)d_in[3];
    const int*   ed    = (const int*)d_in[4];
    const int*   users = (const int*)d_in[5];

    int nu    = in_sizes[0] / D;
    int ni    = in_sizes[1] / D;
    int nnz   = in_sizes[2];
    int batch = in_sizes[5];
    int n_nodes = nu + ni;
    int total = n_nodes * D;
    int nipad = ((ni + 127) / 128) * 128;

    float *x, *y, *acc, *eval;
    int *cnt, *off, *cur, *bsum, *esrc;
    __nv_bfloat16 *Ap, *Bp;
    cudaGetSymbolAddress((void**)&x,    g_x);
    cudaGetSymbolAddress((void**)&y,    g_y);
    cudaGetSymbolAddress((void**)&acc,  g_acc);
    cudaGetSymbolAddress((void**)&cnt,  g_cnt);
    cudaGetSymbolAddress((void**)&off,  g_off);
    cudaGetSymbolAddress((void**)&cur,  g_cur);
    cudaGetSymbolAddress((void**)&bsum, g_bsum);
    cudaGetSymbolAddress((void**)&eval, g_eval);
    cudaGetSymbolAddress((void**)&esrc, g_esrc);
    cudaGetSymbolAddress((void**)&Ap,   g_Ap);
    cudaGetSymbolAddress((void**)&Bp,   g_Bp);

    // --- init + CSR build ---
    zero_cnt_kernel<<<(n_nodes + 255) / 256, 256>>>(cnt, n_nodes);
    init_kernel<<<(total / 4 + 255) / 256, 256>>>(ue, ie, x, acc, nu * D, total);
    hist_kernel<<<(nnz + 255) / 256, 256>>>(ed, cnt, nnz);

    int nb = (n_nodes + 1023) / 1024;
    scan_blocks_kernel<<<nb, 1024>>>(cnt, off, bsum, n_nodes);
    scan_bsum_kernel<<<1, 1024>>>(bsum, nb);
    scan_add_kernel<<<(n_nodes + 255) / 256, 256>>>(off, cur, bsum, n_nodes);
    scatter_kernel<<<(nnz + 255) / 256, 256>>>(ev, es, ed, cur, eval, esrc, nnz);

    // --- 3 propagation layers ---
    float* curx = x;
    float* nxt  = y;
    for (int l = 0; l < 3; l++) {
        long long t = (long long)n_nodes * 32;
        int blocks = (int)((t + 255) / 256);
        spmm_csr_kernel<<<blocks, 256>>>(curx, nxt, acc, off, cnt, eval, esrc, n_nodes);
        float* tmp = curx; curx = nxt; nxt = tmp;
    }

    // --- split-precision operand build ---
    {
        int ta = batch * (GK / 2);
        buildA_kernel<<<(ta + 255) / 256, 256>>>(acc, users, Ap, batch);
        int tb = nipad * (GK / 2);
        buildB_kernel<<<(tb + 255) / 256, 256>>>(acc, Bp, nu, ni, nipad);
    }

    // --- HMMA rating GEMM ---
    cudaFuncSetAttribute(gemm_mma_kernel, cudaFuncAttributeMaxDynamicSharedMemorySize,
                         GEMM_SMEM_TOT);
    dim3 grid(nipad / 128, (batch + 127) / 128);
    gemm_mma_kernel<<<grid, 256, GEMM_SMEM_TOT>>>(Ap, Bp, (float*)d_out, batch, ni);
}

// round 5
// speedup vs baseline: 1.9721x; 1.0423x over previous
#include <cuda_runtime.h>
#include <cuda_bf16.h>
#include <cuda_fp16.h>
#include <cstdint>

#define D 64
#define NCAP 160000
#define ECAP 4200000
#define GK 192            // split-K: A'=[hi,hi,lo], B'=[hi,lo,hi]
#define APCAP (4096 * GK)
#define BPCAP (51200 * GK)

// Scratch (allocation-free rule: __device__ globals).
__device__ __half g_xh[NCAP * D];     // propagated features, fp16 storage
__device__ __half g_yh[NCAP * D];
__device__ float  g_acc[NCAP * D];    // fp32 accumulator
__device__ int    g_cnt[NCAP];
__device__ int    g_off[NCAP];
__device__ int    g_cur[NCAP];
__device__ int    g_bsum[1024];
__device__ float  g_eval[ECAP];
__device__ int    g_esrc[ECAP];
__device__ __nv_bfloat16 g_Ap[APCAP];
__device__ __nv_bfloat16 g_Bp[BPCAP];

// ---------------------------------------------------------------------------
__global__ void zero_cnt_kernel(int* __restrict__ cnt, int n) {
    int i = blockIdx.x * blockDim.x + threadIdx.x;
    if (i < n) cnt[i] = 0;
}

// init: acc = concat(ue, ie) fp32; xh = fp16 of same
__global__ void init_kernel(const float* __restrict__ ue, const float* __restrict__ ie,
                            __half* __restrict__ xh, float* __restrict__ acc,
                            int nu_elems, int total_elems) {
    int i = (blockIdx.x * blockDim.x + threadIdx.x) * 4;
    if (i >= total_elems) return;
    float4 v = (i < nu_elems) ? *(const float4*)(ue + i)
                              : *(const float4*)(ie + (i - nu_elems));
    *(float4*)(acc + i) = v;
    __half2 h0 = __floats2half2_rn(v.x, v.y);
    __half2 h1 = __floats2half2_rn(v.z, v.w);
    *(__half2*)(xh + i)     = h0;
    *(__half2*)(xh + i + 2) = h1;
}

// ---------------------------------------------------------------------------
// CSR build
// ---------------------------------------------------------------------------
__global__ void hist_kernel(const int* __restrict__ ed, int* __restrict__ cnt, int nnz) {
    int e = blockIdx.x * blockDim.x + threadIdx.x;
    if (e < nnz) atomicAdd(&cnt[ed[e]], 1);
}

__global__ void scan_blocks_kernel(const int* __restrict__ cnt, int* __restrict__ off,
                                   int* __restrict__ bsum, int n) {
    __shared__ int s[1024];
    int tid = threadIdx.x;
    int gid = blockIdx.x * 1024 + tid;
    int v = (gid < n) ? cnt[gid] : 0;
    s[tid] = v;
    __syncthreads();
    #pragma unroll
    for (int o = 1; o < 1024; o <<= 1) {
        int t = (tid >= o) ? s[tid - o] : 0;
        __syncthreads();
        s[tid] += t;
        __syncthreads();
    }
    if (gid < n) off[gid] = s[tid] - v;
    if (tid == 1023) bsum[blockIdx.x] = s[1023];
}

__global__ void scan_bsum_kernel(int* __restrict__ bsum, int nb) {
    __shared__ int s[1024];
    int tid = threadIdx.x;
    int v = (tid < nb) ? bsum[tid] : 0;
    s[tid] = v;
    __syncthreads();
    #pragma unroll
    for (int o = 1; o < 1024; o <<= 1) {
        int t = (tid >= o) ? s[tid - o] : 0;
        __syncthreads();
        s[tid] += t;
        __syncthreads();
    }
    if (tid < nb) bsum[tid] = s[tid] - v;
}

__global__ void scan_add_kernel(int* __restrict__ off, int* __restrict__ cur,
                                const int* __restrict__ bsum, int n) {
    int gid = blockIdx.x * blockDim.x + threadIdx.x;
    if (gid < n) {
        int o = off[gid] + bsum[gid >> 10];
        off[gid] = o;
        cur[gid] = o;
    }
}

__global__ void scatter_kernel(const float* __restrict__ ev, const int* __restrict__ es,
                               const int* __restrict__ ed, int* __restrict__ cur,
                               float* __restrict__ oval, int* __restrict__ osrc, int nnz) {
    int e = blockIdx.x * blockDim.x + threadIdx.x;
    if (e < nnz) {
        int d = ed[e];
        int p = atomicAdd(&cur[d], 1);
        oval[p] = ev[e];
        osrc[p] = es[e];
    }
}

// ---------------------------------------------------------------------------
// CSR SPMM (fp16 storage, fp32 math), one warp per node, atomic-free.
//   y[n] = sum val*x[src];  yh = fp16(y);  acc[n] += y (fp32)
// Each lane owns 2 feature columns (half2 gather = 4B -> 128B/row coalesced).
// ---------------------------------------------------------------------------
__global__ void __launch_bounds__(256)
spmm_csr_kernel(const __half* __restrict__ xh, __half* __restrict__ yh,
                float* __restrict__ accb,
                const int* __restrict__ off, const int* __restrict__ cnt,
                const float* __restrict__ eval, const int* __restrict__ esrc,
                int n_nodes) {
    int warp = (blockIdx.x * blockDim.x + threadIdx.x) >> 5;
    int lane = threadIdx.x & 31;
    if (warp >= n_nodes) return;

    int start = __ldg(off + warp);
    int deg   = __ldg(cnt + warp);

    float a0 = 0.f, a1 = 0.f;
    for (int base = 0; base < deg; base += 32) {
        int m = deg - base;
        if (m > 32) m = 32;
        float evv = 0.f;
        int   esv = 0;
        if (lane < m) {
            evv = __ldg(eval + start + base + lane);
            esv = __ldg(esrc + start + base + lane);
        }
        #pragma unroll 4
        for (int t = 0; t < m; t++) {
            float v = __shfl_sync(0xffffffff, evv, t);
            int   s = __shfl_sync(0xffffffff, esv, t);
            __half2 h = *(const __half2*)(xh + (size_t)s * D + lane * 2);
            float2 xv = __half22float2(h);
            a0 += v * xv.x;
            a1 += v * xv.y;
        }
    }

    size_t o = (size_t)warp * D + lane * 2;
    *(__half2*)(yh + o) = __floats2half2_rn(a0, a1);
    float2 ac = *(float2*)(accb + o);
    ac.x += a0;
    ac.y += a1;
    *(float2*)(accb + o) = ac;
}

// ---------------------------------------------------------------------------
// Split-precision conversion:  v = hi(bf16) + lo(bf16)
// ---------------------------------------------------------------------------
__device__ __forceinline__ void split2(float a0, float a1,
                                       __nv_bfloat162* hi, __nv_bfloat162* lo) {
    __nv_bfloat16 h0 = __float2bfloat16_rn(a0);
    __nv_bfloat16 h1 = __float2bfloat16_rn(a1);
    __nv_bfloat16 l0 = __float2bfloat16_rn(a0 - __bfloat162float(h0));
    __nv_bfloat16 l1 = __float2bfloat16_rn(a1 - __bfloat162float(h1));
    *hi = __nv_bfloat162(h0, h1);
    *lo = __nv_bfloat162(l0, l1);
}

__global__ void buildA_kernel(const float* __restrict__ acc, const int* __restrict__ users,
                              __nv_bfloat16* __restrict__ Ap, int batch) {
    int idx = blockIdx.x * blockDim.x + threadIdx.x;
    int total = batch * (GK / 2);
    if (idx >= total) return;
    int b = idx / (GK / 2), c2 = idx % (GK / 2);
    int sec = (c2 * 2) / D, k = (c2 * 2) % D;
    int u = __ldg(users + b);
    float2 v = *(const float2*)(acc + (size_t)u * D + k);
    __nv_bfloat162 hi, lo;
    split2(v.x, v.y, &hi, &lo);
    *(__nv_bfloat162*)(Ap + (size_t)b * GK + c2 * 2) = (sec == 2) ? lo : hi;
}

__global__ void buildB_kernel(const float* __restrict__ acc, __nv_bfloat16* __restrict__ Bp,
                              int nu, int ni, int nipad) {
    int idx = blockIdx.x * blockDim.x + threadIdx.x;
    int total = nipad * (GK / 2);
    if (idx >= total) return;
    int j = idx / (GK / 2), c2 = idx % (GK / 2);
    int sec = (c2 * 2) / D, k = (c2 * 2) % D;
    float2 v = make_float2(0.f, 0.f);
    if (j < ni) v = *(const float2*)(acc + (size_t)(nu + j) * D + k);
    __nv_bfloat162 hi, lo;
    split2(v.x, v.y, &hi, &lo);
    *(__nv_bfloat162*)(Bp + (size_t)j * GK + c2 * 2) = (sec == 1) ? lo : hi;
}

// ---------------------------------------------------------------------------
// HMMA GEMM: out[128x128] tile = A'[128,192] . B'[128,192]^T / 16
// 8 warps 2x4, each 64x32. cp.async tile fill. ROWB=400 -> conflict-free.
// ---------------------------------------------------------------------------
#define ROWB 400
#define BOFF (128 * ROWB)
#define GEMM_SMEM_TOT (2 * 128 * ROWB)   // 102400

__device__ __forceinline__ uint32_t smem_u32(const void* p) {
    uint32_t a;
    asm("{ .reg .u64 t; cvta.to.shared.u64 t, %1; cvt.u32.u64 %0, t; }"
        : "=r"(a) : "l"(p));
    return a;
}

__global__ void __launch_bounds__(256, 2)
gemm_mma_kernel(const __nv_bfloat16* __restrict__ Ap, const __nv_bfloat16* __restrict__ Bp,
                float* __restrict__ out, int batch, int n_items) {
    extern __shared__ char smem[];
    uint32_t sbase = smem_u32(smem);
    int tid = threadIdx.x;
    int wid = tid >> 5;
    int lane = tid & 31;
    int bm = blockIdx.y, bn = blockIdx.x;

    // cp.async tile fill: 128 rows x 24 16B-chunks each for A and B.
    const char* Agp = (const char*)(Ap + (size_t)bm * 128 * GK);
    const char* Bgp = (const char*)(Bp + (size_t)bn * 128 * GK);
    #pragma unroll 4
    for (int i = tid; i < 128 * 24; i += 256) {
        int r = i / 24, c = i % 24;
        uint32_t sa = sbase + r * ROWB + c * 16;
        uint32_t sb = sa + BOFF;
        asm volatile("cp.async.cg.shared.global [%0], [%1], 16;"
                     :: "r"(sa), "l"(Agp + r * 384 + c * 16));
        asm volatile("cp.async.cg.shared.global [%0], [%1], 16;"
                     :: "r"(sb), "l"(Bgp + r * 384 + c * 16));
    }
    asm volatile("cp.async.commit_group;");
    asm volatile("cp.async.wait_group 0;");
    __syncthreads();

    int wm = (wid >> 2) * 64;
    int wn = (wid & 3) * 32;

    float c[4][4][4];
    #pragma unroll
    for (int mt = 0; mt < 4; mt++)
        #pragma unroll
        for (int nt = 0; nt < 4; nt++)
            #pragma unroll
            for (int q = 0; q < 4; q++) c[mt][nt][q] = 0.f;

    uint32_t a_row = wm + (lane & 15);
    uint32_t a_kb  = (lane & 16) ? 16u : 0u;
    uint32_t b_row = wn + (lane & 7);
    uint32_t b_kb  = (lane & 8) ? 16u : 0u;

    #pragma unroll
    for (int ks = 0; ks < 12; ks++) {
        uint32_t kb = ks * 32;
        uint32_t a[4][4], b[4][2];
        #pragma unroll
        for (int mt = 0; mt < 4; mt++) {
            uint32_t addr = sbase + (a_row + mt * 16) * ROWB + kb + a_kb;
            asm volatile("ldmatrix.sync.aligned.m8n8.x4.shared.b16 {%0,%1,%2,%3}, [%4];"
                         : "=r"(a[mt][0]), "=r"(a[mt][1]), "=r"(a[mt][2]), "=r"(a[mt][3])
                         : "r"(addr));
        }
        #pragma unroll
        for (int nt = 0; nt < 4; nt++) {
            uint32_t addr = sbase + BOFF + (b_row + nt * 8) * ROWB + kb + b_kb;
            asm volatile("ldmatrix.sync.aligned.m8n8.x2.shared.b16 {%0,%1}, [%2];"
                         : "=r"(b[nt][0]), "=r"(b[nt][1])
                         : "r"(addr));
        }
        #pragma unroll
        for (int mt = 0; mt < 4; mt++)
            #pragma unroll
            for (int nt = 0; nt < 4; nt++) {
                asm volatile(
                    "mma.sync.aligned.m16n8k16.row.col.f32.bf16.bf16.f32 "
                    "{%0,%1,%2,%3}, {%4,%5,%6,%7}, {%8,%9}, {%0,%1,%2,%3};"
                    : "+f"(c[mt][nt][0]), "+f"(c[mt][nt][1]),
                      "+f"(c[mt][nt][2]), "+f"(c[mt][nt][3])
                    : "r"(a[mt][0]), "r"(a[mt][1]), "r"(a[mt][2]), "r"(a[mt][3]),
                      "r"(b[nt][0]), "r"(b[nt][1]));
            }
    }

    const float S = 0.0625f;
    int gr = lane >> 2;
    int gc = (lane & 3) * 2;
    #pragma unroll
    for (int mt = 0; mt < 4; mt++) {
        int m0 = bm * 128 + wm + mt * 16 + gr;
        int m1 = m0 + 8;
        #pragma unroll
        for (int nt = 0; nt < 4; nt++) {
            int n = bn * 128 + wn + nt * 8 + gc;
            if (n < n_items) {
                if (m0 < batch)
                    *(float2*)(out + (size_t)m0 * n_items + n) =
                        make_float2(c[mt][nt][0] * S, c[mt][nt][1] * S);
                if (m1 < batch)
                    *(float2*)(out + (size_t)m1 * n_items + n) =
                        make_float2(c[mt][nt][2] * S, c[mt][nt][3] * S);
            }
        }
    }
}

// ---------------------------------------------------------------------------
extern "C" void kernel_launch(void* const* d_in, const int* in_sizes, int n_in,
                              void* d_out, int out_size) {
    const float* ue    = (const float*)d_in[0];
    const float* ie    = (const float*)d_in[1];
    const float* ev    = (const float*)d_in[2];
    const int*   es    = (const int*)d_in[3];
    const int*   ed    = (const int*)d_in[4];
    const int*   users = (const int*)d_in[5];

    int nu    = in_sizes[0] / D;
    int ni    = in_sizes[1] / D;
    int nnz   = in_sizes[2];
    int batch = in_sizes[5];
    int n_nodes = nu + ni;
    int total = n_nodes * D;
    int nipad = ((ni + 127) / 128) * 128;

    __half *xh, *yh;
    float *acc, *eval;
    int *cnt, *off, *cur, *bsum, *esrc;
    __nv_bfloat16 *Ap, *Bp;
    cudaGetSymbolAddress((void**)&xh,   g_xh);
    cudaGetSymbolAddress((void**)&yh,   g_yh);
    cudaGetSymbolAddress((void**)&acc,  g_acc);
    cudaGetSymbolAddress((void**)&cnt,  g_cnt);
    cudaGetSymbolAddress((void**)&off,  g_off);
    cudaGetSymbolAddress((void**)&cur,  g_cur);
    cudaGetSymbolAddress((void**)&bsum, g_bsum);
    cudaGetSymbolAddress((void**)&eval, g_eval);
    cudaGetSymbolAddress((void**)&esrc, g_esrc);
    cudaGetSymbolAddress((void**)&Ap,   g_Ap);
    cudaGetSymbolAddress((void**)&Bp,   g_Bp);

    // --- init + CSR build ---
    zero_cnt_kernel<<<(n_nodes + 255) / 256, 256>>>(cnt, n_nodes);
    init_kernel<<<(total / 4 + 255) / 256, 256>>>(ue, ie, xh, acc, nu * D, total);
    hist_kernel<<<(nnz + 255) / 256, 256>>>(ed, cnt, nnz);

    int nb = (n_nodes + 1023) / 1024;
    scan_blocks_kernel<<<nb, 1024>>>(cnt, off, bsum, n_nodes);
    scan_bsum_kernel<<<1, 1024>>>(bsum, nb);
    scan_add_kernel<<<(n_nodes + 255) / 256, 256>>>(off, cur, bsum, n_nodes);
    scatter_kernel<<<(nnz + 255) / 256, 256>>>(ev, es, ed, cur, eval, esrc, nnz);

    // --- 3 propagation layers ---
    __half* curx = xh;
    __half* nxt  = yh;
    for (int l = 0; l < 3; l++) {
        long long t = (long long)n_nodes * 32;
        int blocks = (int)((t + 255) / 256);
        spmm_csr_kernel<<<blocks, 256>>>(curx, nxt, acc, off, cnt, eval, esrc, n_nodes);
        __half* tmp = curx; curx = nxt; nxt = tmp;
    }

    // --- split-precision operand build ---
    {
        int ta = batch * (GK / 2);
        buildA_kernel<<<(ta + 255) / 256, 256>>>(acc, users, Ap, batch);
        int tb = nipad * (GK / 2);
        buildB_kernel<<<(tb + 255) / 256, 256>>>(acc, Bp, nu, ni, nipad);
    }

    // --- HMMA rating GEMM ---
    cudaFuncSetAttribute(gemm_mma_kernel, cudaFuncAttributeMaxDynamicSharedMemorySize,
                         GEMM_SMEM_TOT);
    dim3 grid(nipad / 128, (batch + 127) / 128);
    gemm_mma_kernel<<<grid, 256, GEMM_SMEM_TOT>>>(Ap, Bp, (float*)d_out, batch, ni);
}

// round 6
// speedup vs baseline: 2.2032x; 1.1172x over previous
#include <cuda_runtime.h>
#include <cuda_bf16.h>
#include <cuda_fp16.h>
#include <cstdint>

#define D 64
#define NCAP 160000
#define ECAP 4200000
#define GK 192            // split-K: A'=[hi,hi,lo], B'=[hi,lo,hi]
#define APCAP (4096 * GK)
#define BPCAP (51200 * GK)

// Scratch (allocation-free rule: __device__ globals).
__device__ __half g_xh[NCAP * D];     // propagated features, fp16 storage
__device__ __half g_yh[NCAP * D];
__device__ float  g_acc[NCAP * D];    // fp32 accumulator
__device__ int    g_cnt[NCAP];
__device__ int    g_off[NCAP];
__device__ int    g_cur[NCAP];
__device__ int    g_bsum[1024];
__device__ int2   g_epack[ECAP];      // dst-sorted {src, val bits}
__device__ __nv_bfloat16 g_Ap[APCAP];
__device__ __nv_bfloat16 g_Bp[BPCAP];

// ---------------------------------------------------------------------------
__global__ void zero_cnt_kernel(int* __restrict__ cnt, int n) {
    int i = blockIdx.x * blockDim.x + threadIdx.x;
    if (i < n) cnt[i] = 0;
}

// init: acc = concat(ue, ie) fp32; xh = fp16 of same
__global__ void init_kernel(const float* __restrict__ ue, const float* __restrict__ ie,
                            __half* __restrict__ xh, float* __restrict__ acc,
                            int nu_elems, int total_elems) {
    int i = (blockIdx.x * blockDim.x + threadIdx.x) * 4;
    if (i >= total_elems) return;
    float4 v = (i < nu_elems) ? *(const float4*)(ue + i)
                              : *(const float4*)(ie + (i - nu_elems));
    *(float4*)(acc + i) = v;
    *(__half2*)(xh + i)     = __floats2half2_rn(v.x, v.y);
    *(__half2*)(xh + i + 2) = __floats2half2_rn(v.z, v.w);
}

// ---------------------------------------------------------------------------
// CSR build
// ---------------------------------------------------------------------------
__global__ void hist_kernel(const int* __restrict__ ed, int* __restrict__ cnt, int nnz) {
    int e = blockIdx.x * blockDim.x + threadIdx.x;
    if (e < nnz) atomicAdd(&cnt[ed[e]], 1);
}

__global__ void scan_blocks_kernel(const int* __restrict__ cnt, int* __restrict__ off,
                                   int* __restrict__ bsum, int n) {
    __shared__ int s[1024];
    int tid = threadIdx.x;
    int gid = blockIdx.x * 1024 + tid;
    int v = (gid < n) ? cnt[gid] : 0;
    s[tid] = v;
    __syncthreads();
    #pragma unroll
    for (int o = 1; o < 1024; o <<= 1) {
        int t = (tid >= o) ? s[tid - o] : 0;
        __syncthreads();
        s[tid] += t;
        __syncthreads();
    }
    if (gid < n) off[gid] = s[tid] - v;
    if (tid == 1023) bsum[blockIdx.x] = s[1023];
}

__global__ void scan_bsum_kernel(int* __restrict__ bsum, int nb) {
    __shared__ int s[1024];
    int tid = threadIdx.x;
    int v = (tid < nb) ? bsum[tid] : 0;
    s[tid] = v;
    __syncthreads();
    #pragma unroll
    for (int o = 1; o < 1024; o <<= 1) {
        int t = (tid >= o) ? s[tid - o] : 0;
        __syncthreads();
        s[tid] += t;
        __syncthreads();
    }
    if (tid < nb) bsum[tid] = s[tid] - v;
}

__global__ void scan_add_kernel(int* __restrict__ off, int* __restrict__ cur,
                                const int* __restrict__ bsum, int n) {
    int gid = blockIdx.x * blockDim.x + threadIdx.x;
    if (gid < n) {
        int o = off[gid] + bsum[gid >> 10];
        off[gid] = o;
        cur[gid] = o;
    }
}

__global__ void scatter_kernel(const float* __restrict__ ev, const int* __restrict__ es,
                               const int* __restrict__ ed, int* __restrict__ cur,
                               int2* __restrict__ epack, int nnz) {
    int e = blockIdx.x * blockDim.x + threadIdx.x;
    if (e < nnz) {
        int d = ed[e];
        int p = atomicAdd(&cur[d], 1);
        epack[p] = make_int2(es[e], __float_as_int(ev[e]));
    }
}

// ---------------------------------------------------------------------------
// CSR SPMM (fp16 storage, fp32 math), one warp per node, 8 lanes per edge.
// Warp processes 4 edges/iteration: subgroup g = lane>>3 handles edge t*4+g,
// each lane loads uint4 (8 halves = 16B) of the source row.
// ---------------------------------------------------------------------------
__global__ void __launch_bounds__(256)
spmm_csr_kernel(const __half* __restrict__ xh, __half* __restrict__ yh,
                float* __restrict__ accb,
                const int* __restrict__ off, const int* __restrict__ cnt,
                const int2* __restrict__ epack, int n_nodes) {
    int warp = (blockIdx.x * blockDim.x + threadIdx.x) >> 5;
    int lane = threadIdx.x & 31;
    if (warp >= n_nodes) return;

    int start = __ldg(off + warp);
    int deg   = __ldg(cnt + warp);

    int sub  = lane >> 3;        // subgroup 0..3 (edge within quad)
    int col8 = (lane & 7) * 8;   // feature column base (8 halves)

    float a[8];
    #pragma unroll
    for (int i = 0; i < 8; i++) a[i] = 0.f;

    for (int base = 0; base < deg; base += 32) {
        int m = deg - base;
        if (m > 32) m = 32;
        int   esv = 0;
        float evv = 0.f;
        if (lane < m) {
            int2 md = __ldg(epack + start + base + lane);
            esv = md.x;
            evv = __int_as_float(md.y);
        }
        int iters = (m + 3) >> 2;
        #pragma unroll 4
        for (int t = 0; t < iters; t++) {
            int idx = t * 4 + sub;
            float v = __shfl_sync(0xffffffff, evv, idx);
            int   s = __shfl_sync(0xffffffff, esv, idx);
            uint4 raw = *(const uint4*)(xh + (size_t)s * D + col8);
            const __half2* h = (const __half2*)&raw;
            #pragma unroll
            for (int q = 0; q < 4; q++) {
                float2 f = __half22float2(h[q]);
                a[q * 2 + 0] += v * f.x;
                a[q * 2 + 1] += v * f.y;
            }
        }
    }

    // combine the 4 subgroups (lanes l, l+8, l+16, l+24 share columns)
    #pragma unroll
    for (int i = 0; i < 8; i++) {
        a[i] += __shfl_down_sync(0xffffffff, a[i], 16);
        a[i] += __shfl_down_sync(0xffffffff, a[i], 8);
    }

    if (lane < 8) {
        size_t o = (size_t)warp * D + lane * 8;
        // y as fp16 (8 halves)
        __half2 hp[4];
        #pragma unroll
        for (int q = 0; q < 4; q++) hp[q] = __floats2half2_rn(a[q * 2], a[q * 2 + 1]);
        *(uint4*)(yh + o) = *(uint4*)hp;
        // acc += y (fp32)
        float4 c0 = *(float4*)(accb + o);
        float4 c1 = *(float4*)(accb + o + 4);
        c0.x += a[0]; c0.y += a[1]; c0.z += a[2]; c0.w += a[3];
        c1.x += a[4]; c1.y += a[5]; c1.z += a[6]; c1.w += a[7];
        *(float4*)(accb + o)     = c0;
        *(float4*)(accb + o + 4) = c1;
    }
}

// ---------------------------------------------------------------------------
// Split-precision conversion:  v = hi(bf16) + lo(bf16)
// ---------------------------------------------------------------------------
__device__ __forceinline__ void split2(float a0, float a1,
                                       __nv_bfloat162* hi, __nv_bfloat162* lo) {
    __nv_bfloat16 h0 = __float2bfloat16_rn(a0);
    __nv_bfloat16 h1 = __float2bfloat16_rn(a1);
    __nv_bfloat16 l0 = __float2bfloat16_rn(a0 - __bfloat162float(h0));
    __nv_bfloat16 l1 = __float2bfloat16_rn(a1 - __bfloat162float(h1));
    *hi = __nv_bfloat162(h0, h1);
    *lo = __nv_bfloat162(l0, l1);
}

__global__ void buildA_kernel(const float* __restrict__ acc, const int* __restrict__ users,
                              __nv_bfloat16* __restrict__ Ap, int batch) {
    int idx = blockIdx.x * blockDim.x + threadIdx.x;
    int total = batch * (GK / 2);
    if (idx >= total) return;
    int b = idx / (GK / 2), c2 = idx % (GK / 2);
    int sec = (c2 * 2) / D, k = (c2 * 2) % D;
    int u = __ldg(users + b);
    float2 v = *(const float2*)(acc + (size_t)u * D + k);
    __nv_bfloat162 hi, lo;
    split2(v.x, v.y, &hi, &lo);
    *(__nv_bfloat162*)(Ap + (size_t)b * GK + c2 * 2) = (sec == 2) ? lo : hi;
}

__global__ void buildB_kernel(const float* __restrict__ acc, __nv_bfloat16* __restrict__ Bp,
                              int nu, int ni, int nipad) {
    int idx = blockIdx.x * blockDim.x + threadIdx.x;
    int total = nipad * (GK / 2);
    if (idx >= total) return;
    int j = idx / (GK / 2), c2 = idx % (GK / 2);
    int sec = (c2 * 2) / D, k = (c2 * 2) % D;
    float2 v = make_float2(0.f, 0.f);
    if (j < ni) v = *(const float2*)(acc + (size_t)(nu + j) * D + k);
    __nv_bfloat162 hi, lo;
    split2(v.x, v.y, &hi, &lo);
    *(__nv_bfloat162*)(Bp + (size_t)j * GK + c2 * 2) = (sec == 1) ? lo : hi;
}

// ---------------------------------------------------------------------------
// HMMA GEMM: out[128x128] tile = A'[128,192] . B'[128,192]^T / 16
// 8 warps 2x4, each 64x32. cp.async tile fill. ROWB=400 -> conflict-free.
// ---------------------------------------------------------------------------
#define ROWB 400
#define BOFF (128 * ROWB)
#define GEMM_SMEM_TOT (2 * 128 * ROWB)   // 102400

__device__ __forceinline__ uint32_t smem_u32(const void* p) {
    uint32_t a;
    asm("{ .reg .u64 t; cvta.to.shared.u64 t, %1; cvt.u32.u64 %0, t; }"
        : "=r"(a) : "l"(p));
    return a;
}

__global__ void __launch_bounds__(256, 2)
gemm_mma_kernel(const __nv_bfloat16* __restrict__ Ap, const __nv_bfloat16* __restrict__ Bp,
                float* __restrict__ out, int batch, int n_items) {
    extern __shared__ char smem[];
    uint32_t sbase = smem_u32(smem);
    int tid = threadIdx.x;
    int wid = tid >> 5;
    int lane = tid & 31;
    int bm = blockIdx.y, bn = blockIdx.x;

    const char* Agp = (const char*)(Ap + (size_t)bm * 128 * GK);
    const char* Bgp = (const char*)(Bp + (size_t)bn * 128 * GK);
    #pragma unroll 4
    for (int i = tid; i < 128 * 24; i += 256) {
        int r = i / 24, c = i % 24;
        uint32_t sa = sbase + r * ROWB + c * 16;
        uint32_t sb = sa + BOFF;
        asm volatile("cp.async.cg.shared.global [%0], [%1], 16;"
                     :: "r"(sa), "l"(Agp + r * 384 + c * 16));
        asm volatile("cp.async.cg.shared.global [%0], [%1], 16;"
                     :: "r"(sb), "l"(Bgp + r * 384 + c * 16));
    }
    asm volatile("cp.async.commit_group;");
    asm volatile("cp.async.wait_group 0;");
    __syncthreads();

    int wm = (wid >> 2) * 64;
    int wn = (wid & 3) * 32;

    float c[4][4][4];
    #pragma unroll
    for (int mt = 0; mt < 4; mt++)
        #pragma unroll
        for (int nt = 0; nt < 4; nt++)
            #pragma unroll
            for (int q = 0; q < 4; q++) c[mt][nt][q] = 0.f;

    uint32_t a_row = wm + (lane & 15);
    uint32_t a_kb  = (lane & 16) ? 16u : 0u;
    uint32_t b_row = wn + (lane & 7);
    uint32_t b_kb  = (lane & 8) ? 16u : 0u;

    #pragma unroll
    for (int ks = 0; ks < 12; ks++) {
        uint32_t kb = ks * 32;
        uint32_t a[4][4], b[4][2];
        #pragma unroll
        for (int mt = 0; mt < 4; mt++) {
            uint32_t addr = sbase + (a_row + mt * 16) * ROWB + kb + a_kb;
            asm volatile("ldmatrix.sync.aligned.m8n8.x4.shared.b16 {%0,%1,%2,%3}, [%4];"
                         : "=r"(a[mt][0]), "=r"(a[mt][1]), "=r"(a[mt][2]), "=r"(a[mt][3])
                         : "r"(addr));
        }
        #pragma unroll
        for (int nt = 0; nt < 4; nt++) {
            uint32_t addr = sbase + BOFF + (b_row + nt * 8) * ROWB + kb + b_kb;
            asm volatile("ldmatrix.sync.aligned.m8n8.x2.shared.b16 {%0,%1}, [%2];"
                         : "=r"(b[nt][0]), "=r"(b[nt][1])
                         : "r"(addr));
        }
        #pragma unroll
        for (int mt = 0; mt < 4; mt++)
            #pragma unroll
            for (int nt = 0; nt < 4; nt++) {
                asm volatile(
                    "mma.sync.aligned.m16n8k16.row.col.f32.bf16.bf16.f32 "
                    "{%0,%1,%2,%3}, {%4,%5,%6,%7}, {%8,%9}, {%0,%1,%2,%3};"
                    : "+f"(c[mt][nt][0]), "+f"(c[mt][nt][1]),
                      "+f"(c[mt][nt][2]), "+f"(c[mt][nt][3])
                    : "r"(a[mt][0]), "r"(a[mt][1]), "r"(a[mt][2]), "r"(a[mt][3]),
                      "r"(b[nt][0]), "r"(b[nt][1]));
            }
    }

    const float S = 0.0625f;
    int gr = lane >> 2;
    int gc = (lane & 3) * 2;
    #pragma unroll
    for (int mt = 0; mt < 4; mt++) {
        int m0 = bm * 128 + wm + mt * 16 + gr;
        int m1 = m0 + 8;
        #pragma unroll
        for (int nt = 0; nt < 4; nt++) {
            int n = bn * 128 + wn + nt * 8 + gc;
            if (n < n_items) {
                if (m0 < batch)
                    *(float2*)(out + (size_t)m0 * n_items + n) =
                        make_float2(c[mt][nt][0] * S, c[mt][nt][1] * S);
                if (m1 < batch)
                    *(float2*)(out + (size_t)m1 * n_items + n) =
                        make_float2(c[mt][nt][2] * S, c[mt][nt][3] * S);
            }
        }
    }
}

// ---------------------------------------------------------------------------
extern "C" void kernel_launch(void* const* d_in, const int* in_sizes, int n_in,
                              void* d_out, int out_size) {
    const float* ue    = (const float*)d_in[0];
    const float* ie    = (const float*)d_in[1];
    const float* ev    = (const float*)d_in[2];
    const int*   es    = (const int*)d_in[3];
    const int*   ed    = (const int*)d_in[4];
    const int*   users = (const int*)d_in[5];

    int nu    = in_sizes[0] / D;
    int ni    = in_sizes[1] / D;
    int nnz   = in_sizes[2];
    int batch = in_sizes[5];
    int n_nodes = nu + ni;
    int total = n_nodes * D;
    int nipad = ((ni + 127) / 128) * 128;

    __half *xh, *yh;
    float *acc;
    int *cnt, *off, *cur, *bsum;
    int2 *epack;
    __nv_bfloat16 *Ap, *Bp;
    cudaGetSymbolAddress((void**)&xh,    g_xh);
    cudaGetSymbolAddress((void**)&yh,    g_yh);
    cudaGetSymbolAddress((void**)&acc,   g_acc);
    cudaGetSymbolAddress((void**)&cnt,   g_cnt);
    cudaGetSymbolAddress((void**)&off,   g_off);
    cudaGetSymbolAddress((void**)&cur,   g_cur);
    cudaGetSymbolAddress((void**)&bsum,  g_bsum);
    cudaGetSymbolAddress((void**)&epack, g_epack);
    cudaGetSymbolAddress((void**)&Ap,    g_Ap);
    cudaGetSymbolAddress((void**)&Bp,    g_Bp);

    // --- init + CSR build ---
    zero_cnt_kernel<<<(n_nodes + 255) / 256, 256>>>(cnt, n_nodes);
    init_kernel<<<(total / 4 + 255) / 256, 256>>>(ue, ie, xh, acc, nu * D, total);
    hist_kernel<<<(nnz + 255) / 256, 256>>>(ed, cnt, nnz);

    int nb = (n_nodes + 1023) / 1024;
    scan_blocks_kernel<<<nb, 1024>>>(cnt, off, bsum, n_nodes);
    scan_bsum_kernel<<<1, 1024>>>(bsum, nb);
    scan_add_kernel<<<(n_nodes + 255) / 256, 256>>>(off, cur, bsum, n_nodes);
    scatter_kernel<<<(nnz + 255) / 256, 256>>>(ev, es, ed, cur, epack, nnz);

    // --- 3 propagation layers ---
    __half* curx = xh;
    __half* nxt  = yh;
    for (int l = 0; l < 3; l++) {
        long long t = (long long)n_nodes * 32;
        int blocks = (int)((t + 255) / 256);
        spmm_csr_kernel<<<blocks, 256>>>(curx, nxt, acc, off, cnt, epack, n_nodes);
        __half* tmp = curx; curx = nxt; nxt = tmp;
    }

    // --- split-precision operand build ---
    {
        int ta = batch * (GK / 2);
        buildA_kernel<<<(ta + 255) / 256, 256>>>(acc, users, Ap, batch);
        int tb = nipad * (GK / 2);
        buildB_kernel<<<(tb + 255) / 256, 256>>>(acc, Bp, nu, ni, nipad);
    }

    // --- HMMA rating GEMM ---
    cudaFuncSetAttribute(gemm_mma_kernel, cudaFuncAttributeMaxDynamicSharedMemorySize,
                         GEMM_SMEM_TOT);
    dim3 grid(nipad / 128, (batch + 127) / 128);
    gemm_mma_kernel<<<grid, 256, GEMM_SMEM_TOT>>>(Ap, Bp, (float*)d_out, batch, ni);
}

// round 7
// speedup vs baseline: 2.2685x; 1.0297x over previous
#include <cuda_runtime.h>
#include <cuda_bf16.h>
#include <cuda_fp16.h>
#include <cstdint>

#define D 64
#define NCAP 160000
#define ECAP 4200000
#define GK 192            // split-K: A'=[hi,hi,lo], B'=[hi,lo,hi]
#define APCAP (4096 * GK)
#define BPCAP (51200 * GK)

// Scratch (allocation-free rule: __device__ globals).
__device__ __half g_xh[NCAP * D];     // propagated features, fp16 storage
__device__ __half g_yh[NCAP * D];
__device__ float  g_acc[NCAP * D];    // fp32 accumulator
__device__ int    g_cnt[NCAP];
__device__ int    g_off[NCAP];
__device__ int    g_cur[NCAP];
__device__ int    g_bsum[1024];
__device__ int2   g_epack[ECAP];      // dst-sorted {src, val bits}
__device__ __nv_bfloat16 g_Ap[APCAP];
__device__ __nv_bfloat16 g_Bp[BPCAP];

// ---------------------------------------------------------------------------
__global__ void zero_cnt_kernel(int* __restrict__ cnt, int n) {
    int i = blockIdx.x * blockDim.x + threadIdx.x;
    if (i < n) cnt[i] = 0;
}

// init: acc = concat(ue, ie) fp32; xh = fp16 of same
__global__ void init_kernel(const float* __restrict__ ue, const float* __restrict__ ie,
                            __half* __restrict__ xh, float* __restrict__ acc,
                            int nu_elems, int total_elems) {
    int i = (blockIdx.x * blockDim.x + threadIdx.x) * 4;
    if (i >= total_elems) return;
    float4 v = (i < nu_elems) ? *(const float4*)(ue + i)
                              : *(const float4*)(ie + (i - nu_elems));
    *(float4*)(acc + i) = v;
    *(__half2*)(xh + i)     = __floats2half2_rn(v.x, v.y);
    *(__half2*)(xh + i + 2) = __floats2half2_rn(v.z, v.w);
}

// ---------------------------------------------------------------------------
// CSR build
// ---------------------------------------------------------------------------
__global__ void hist_kernel(const int* __restrict__ ed, int* __restrict__ cnt, int nnz) {
    int e = blockIdx.x * blockDim.x + threadIdx.x;
    if (e < nnz) atomicAdd(&cnt[ed[e]], 1);
}

__global__ void scan_blocks_kernel(const int* __restrict__ cnt, int* __restrict__ off,
                                   int* __restrict__ bsum, int n) {
    __shared__ int s[1024];
    int tid = threadIdx.x;
    int gid = blockIdx.x * 1024 + tid;
    int v = (gid < n) ? cnt[gid] : 0;
    s[tid] = v;
    __syncthreads();
    #pragma unroll
    for (int o = 1; o < 1024; o <<= 1) {
        int t = (tid >= o) ? s[tid - o] : 0;
        __syncthreads();
        s[tid] += t;
        __syncthreads();
    }
    if (gid < n) off[gid] = s[tid] - v;
    if (tid == 1023) bsum[blockIdx.x] = s[1023];
}

__global__ void scan_bsum_kernel(int* __restrict__ bsum, int nb) {
    __shared__ int s[1024];
    int tid = threadIdx.x;
    int v = (tid < nb) ? bsum[tid] : 0;
    s[tid] = v;
    __syncthreads();
    #pragma unroll
    for (int o = 1; o < 1024; o <<= 1) {
        int t = (tid >= o) ? s[tid - o] : 0;
        __syncthreads();
        s[tid] += t;
        __syncthreads();
    }
    if (tid < nb) bsum[tid] = s[tid] - v;
}

__global__ void scan_add_kernel(int* __restrict__ off, int* __restrict__ cur,
                                const int* __restrict__ bsum, int n) {
    int gid = blockIdx.x * blockDim.x + threadIdx.x;
    if (gid < n) {
        int o = off[gid] + bsum[gid >> 10];
        off[gid] = o;
        cur[gid] = o;
    }
}

__global__ void scatter_kernel(const float* __restrict__ ev, const int* __restrict__ es,
                               const int* __restrict__ ed, int* __restrict__ cur,
                               int2* __restrict__ epack, int nnz) {
    int e = blockIdx.x * blockDim.x + threadIdx.x;
    if (e < nnz) {
        int d = ed[e];
        int p = atomicAdd(&cur[d], 1);
        epack[p] = make_int2(es[e], __float_as_int(ev[e]));
    }
}

// ---------------------------------------------------------------------------
// CSR SPMM (fp16 storage, fp32 math), one warp per node, 8 lanes per edge.
// ---------------------------------------------------------------------------
__global__ void __launch_bounds__(256)
spmm_csr_kernel(const __half* __restrict__ xh, __half* __restrict__ yh,
                float* __restrict__ accb,
                const int* __restrict__ off, const int* __restrict__ cnt,
                const int2* __restrict__ epack, int n_nodes) {
    int warp = (blockIdx.x * blockDim.x + threadIdx.x) >> 5;
    int lane = threadIdx.x & 31;
    if (warp >= n_nodes) return;

    int start = __ldg(off + warp);
    int deg   = __ldg(cnt + warp);

    int sub  = lane >> 3;
    int col8 = (lane & 7) * 8;

    float a[8];
    #pragma unroll
    for (int i = 0; i < 8; i++) a[i] = 0.f;

    for (int base = 0; base < deg; base += 32) {
        int m = deg - base;
        if (m > 32) m = 32;
        int   esv = 0;
        float evv = 0.f;
        if (lane < m) {
            int2 md = __ldg(epack + start + base + lane);
            esv = md.x;
            evv = __int_as_float(md.y);
        }
        int iters = (m + 3) >> 2;
        #pragma unroll 4
        for (int t = 0; t < iters; t++) {
            int idx = t * 4 + sub;
            float v = __shfl_sync(0xffffffff, evv, idx);
            int   s = __shfl_sync(0xffffffff, esv, idx);
            uint4 raw = *(const uint4*)(xh + (size_t)s * D + col8);
            const __half2* h = (const __half2*)&raw;
            #pragma unroll
            for (int q = 0; q < 4; q++) {
                float2 f = __half22float2(h[q]);
                a[q * 2 + 0] += v * f.x;
                a[q * 2 + 1] += v * f.y;
            }
        }
    }

    #pragma unroll
    for (int i = 0; i < 8; i++) {
        a[i] += __shfl_down_sync(0xffffffff, a[i], 16);
        a[i] += __shfl_down_sync(0xffffffff, a[i], 8);
    }

    if (lane < 8) {
        size_t o = (size_t)warp * D + lane * 8;
        __half2 hp[4];
        #pragma unroll
        for (int q = 0; q < 4; q++) hp[q] = __floats2half2_rn(a[q * 2], a[q * 2 + 1]);
        *(uint4*)(yh + o) = *(uint4*)hp;
        float4 c0 = *(float4*)(accb + o);
        float4 c1 = *(float4*)(accb + o + 4);
        c0.x += a[0]; c0.y += a[1]; c0.z += a[2]; c0.w += a[3];
        c1.x += a[4]; c1.y += a[5]; c1.z += a[6]; c1.w += a[7];
        *(float4*)(accb + o)     = c0;
        *(float4*)(accb + o + 4) = c1;
    }
}

// ---------------------------------------------------------------------------
// Split-precision conversion:  v = hi(bf16) + lo(bf16)
// ---------------------------------------------------------------------------
__device__ __forceinline__ void split2(float a0, float a1,
                                       __nv_bfloat162* hi, __nv_bfloat162* lo) {
    __nv_bfloat16 h0 = __float2bfloat16_rn(a0);
    __nv_bfloat16 h1 = __float2bfloat16_rn(a1);
    __nv_bfloat16 l0 = __float2bfloat16_rn(a0 - __bfloat162float(h0));
    __nv_bfloat16 l1 = __float2bfloat16_rn(a1 - __bfloat162float(h1));
    *hi = __nv_bfloat162(h0, h1);
    *lo = __nv_bfloat162(l0, l1);
}

__global__ void buildA_kernel(const float* __restrict__ acc, const int* __restrict__ users,
                              __nv_bfloat16* __restrict__ Ap, int batch) {
    int idx = blockIdx.x * blockDim.x + threadIdx.x;
    int total = batch * (GK / 2);
    if (idx >= total) return;
    int b = idx / (GK / 2), c2 = idx % (GK / 2);
    int sec = (c2 * 2) / D, k = (c2 * 2) % D;
    int u = __ldg(users + b);
    float2 v = *(const float2*)(acc + (size_t)u * D + k);
    __nv_bfloat162 hi, lo;
    split2(v.x, v.y, &hi, &lo);
    *(__nv_bfloat162*)(Ap + (size_t)b * GK + c2 * 2) = (sec == 2) ? lo : hi;
}

__global__ void buildB_kernel(const float* __restrict__ acc, __nv_bfloat16* __restrict__ Bp,
                              int nu, int ni, int nipad) {
    int idx = blockIdx.x * blockDim.x + threadIdx.x;
    int total = nipad * (GK / 2);
    if (idx >= total) return;
    int j = idx / (GK / 2), c2 = idx % (GK / 2);
    int sec = (c2 * 2) / D, k = (c2 * 2) % D;
    float2 v = make_float2(0.f, 0.f);
    if (j < ni) v = *(const float2*)(acc + (size_t)(nu + j) * D + k);
    __nv_bfloat162 hi, lo;
    split2(v.x, v.y, &hi, &lo);
    *(__nv_bfloat162*)(Bp + (size_t)j * GK + c2 * 2) = (sec == 1) ? lo : hi;
}

// ---------------------------------------------------------------------------
// HMMA GEMM with B-tile reuse: each CTA holds one B tile (128 items x 192)
// and iterates MTILES m-tiles of A against it (B L2 traffic / MTILES).
// 8 warps 2x4, each 64x32. ROWB=400 -> conflict-free ldmatrix.
// ---------------------------------------------------------------------------
#define ROWB 400
#define BOFF (128 * ROWB)
#define GEMM_SMEM_TOT (2 * 128 * ROWB)   // 102400
#define MTILES 2

__device__ __forceinline__ uint32_t smem_u32(const void* p) {
    uint32_t a;
    asm("{ .reg .u64 t; cvta.to.shared.u64 t, %1; cvt.u32.u64 %0, t; }"
        : "=r"(a) : "l"(p));
    return a;
}

__global__ void __launch_bounds__(256, 2)
gemm_mma_kernel(const __nv_bfloat16* __restrict__ Ap, const __nv_bfloat16* __restrict__ Bp,
                float* __restrict__ out, int batch, int n_items) {
    extern __shared__ char smem[];
    uint32_t sbase = smem_u32(smem);
    int tid = threadIdx.x;
    int wid = tid >> 5;
    int lane = tid & 31;
    int bn = blockIdx.x;
    int bm0 = blockIdx.y * MTILES;

    // B tile fill (once per CTA)
    const char* Bgp = (const char*)(Bp + (size_t)bn * 128 * GK);
    #pragma unroll 4
    for (int i = tid; i < 128 * 24; i += 256) {
        int r = i / 24, c = i % 24;
        asm volatile("cp.async.cg.shared.global [%0], [%1], 16;"
                     :: "r"(sbase + BOFF + r * ROWB + c * 16), "l"(Bgp + r * 384 + c * 16));
    }

    int wm = (wid >> 2) * 64;
    int wn = (wid & 3) * 32;
    uint32_t a_row = wm + (lane & 15);
    uint32_t a_kb  = (lane & 16) ? 16u : 0u;
    uint32_t b_row = wn + (lane & 7);
    uint32_t b_kb  = (lane & 8) ? 16u : 0u;
    const float S = 0.0625f;
    int gr = lane >> 2;
    int gc = (lane & 3) * 2;

    for (int mi = 0; mi < MTILES; mi++) {
        int bm = bm0 + mi;
        // A tile fill for this m-tile (B persists).
        const char* Agp = (const char*)(Ap + (size_t)bm * 128 * GK);
        #pragma unroll 4
        for (int i = tid; i < 128 * 24; i += 256) {
            int r = i / 24, c = i % 24;
            asm volatile("cp.async.cg.shared.global [%0], [%1], 16;"
                         :: "r"(sbase + r * ROWB + c * 16), "l"(Agp + r * 384 + c * 16));
        }
        asm volatile("cp.async.commit_group;");
        asm volatile("cp.async.wait_group 0;");
        __syncthreads();

        float c[4][4][4];
        #pragma unroll
        for (int mt = 0; mt < 4; mt++)
            #pragma unroll
            for (int nt = 0; nt < 4; nt++)
                #pragma unroll
                for (int q = 0; q < 4; q++) c[mt][nt][q] = 0.f;

        #pragma unroll
        for (int ks = 0; ks < 12; ks++) {
            uint32_t kb = ks * 32;
            uint32_t a[4][4], b[4][2];
            #pragma unroll
            for (int mt = 0; mt < 4; mt++) {
                uint32_t addr = sbase + (a_row + mt * 16) * ROWB + kb + a_kb;
                asm volatile("ldmatrix.sync.aligned.m8n8.x4.shared.b16 {%0,%1,%2,%3}, [%4];"
                             : "=r"(a[mt][0]), "=r"(a[mt][1]), "=r"(a[mt][2]), "=r"(a[mt][3])
                             : "r"(addr));
            }
            #pragma unroll
            for (int nt = 0; nt < 4; nt++) {
                uint32_t addr = sbase + BOFF + (b_row + nt * 8) * ROWB + kb + b_kb;
                asm volatile("ldmatrix.sync.aligned.m8n8.x2.shared.b16 {%0,%1}, [%2];"
                             : "=r"(b[nt][0]), "=r"(b[nt][1])
                             : "r"(addr));
            }
            #pragma unroll
            for (int mt = 0; mt < 4; mt++)
                #pragma unroll
                for (int nt = 0; nt < 4; nt++) {
                    asm volatile(
                        "mma.sync.aligned.m16n8k16.row.col.f32.bf16.bf16.f32 "
                        "{%0,%1,%2,%3}, {%4,%5,%6,%7}, {%8,%9}, {%0,%1,%2,%3};"
                        : "+f"(c[mt][nt][0]), "+f"(c[mt][nt][1]),
                          "+f"(c[mt][nt][2]), "+f"(c[mt][nt][3])
                        : "r"(a[mt][0]), "r"(a[mt][1]), "r"(a[mt][2]), "r"(a[mt][3]),
                          "r"(b[nt][0]), "r"(b[nt][1]));
                }
        }

        #pragma unroll
        for (int mt = 0; mt < 4; mt++) {
            int m0 = bm * 128 + wm + mt * 16 + gr;
            int m1 = m0 + 8;
            #pragma unroll
            for (int nt = 0; nt < 4; nt++) {
                int n = bn * 128 + wn + nt * 8 + gc;
                if (n < n_items) {
                    if (m0 < batch)
                        *(float2*)(out + (size_t)m0 * n_items + n) =
                            make_float2(c[mt][nt][0] * S, c[mt][nt][1] * S);
                    if (m1 < batch)
                        *(float2*)(out + (size_t)m1 * n_items + n) =
                            make_float2(c[mt][nt][2] * S, c[mt][nt][3] * S);
                }
            }
        }
        // ensure all warps done reading A before next iteration overwrites it
        __syncthreads();
    }
}

// ---------------------------------------------------------------------------
extern "C" void kernel_launch(void* const* d_in, const int* in_sizes, int n_in,
                              void* d_out, int out_size) {
    const float* ue    = (const float*)d_in[0];
    const float* ie    = (const float*)d_in[1];
    const float* ev    = (const float*)d_in[2];
    const int*   es    = (const int*)d_in[3];
    const int*   ed    = (const int*)d_in[4];
    const int*   users = (const int*)d_in[5];

    int nu    = in_sizes[0] / D;
    int ni    = in_sizes[1] / D;
    int nnz   = in_sizes[2];
    int batch = in_sizes[5];
    int n_nodes = nu + ni;
    int total = n_nodes * D;
    int nipad = ((ni + 127) / 128) * 128;

    __half *xh, *yh;
    float *acc;
    int *cnt, *off, *cur, *bsum;
    int2 *epack;
    __nv_bfloat16 *Ap, *Bp;
    cudaGetSymbolAddress((void**)&xh,    g_xh);
    cudaGetSymbolAddress((void**)&yh,    g_yh);
    cudaGetSymbolAddress((void**)&acc,   g_acc);
    cudaGetSymbolAddress((void**)&cnt,   g_cnt);
    cudaGetSymbolAddress((void**)&off,   g_off);
    cudaGetSymbolAddress((void**)&cur,   g_cur);
    cudaGetSymbolAddress((void**)&bsum,  g_bsum);
    cudaGetSymbolAddress((void**)&epack, g_epack);
    cudaGetSymbolAddress((void**)&Ap,    g_Ap);
    cudaGetSymbolAddress((void**)&Bp,    g_Bp);

    // --- init + CSR build ---
    zero_cnt_kernel<<<(n_nodes + 255) / 256, 256>>>(cnt, n_nodes);
    init_kernel<<<(total / 4 + 255) / 256, 256>>>(ue, ie, xh, acc, nu * D, total);
    hist_kernel<<<(nnz + 255) / 256, 256>>>(ed, cnt, nnz);

    int nb = (n_nodes + 1023) / 1024;
    scan_blocks_kernel<<<nb, 1024>>>(cnt, off, bsum, n_nodes);
    scan_bsum_kernel<<<1, 1024>>>(bsum, nb);
    scan_add_kernel<<<(n_nodes + 255) / 256, 256>>>(off, cur, bsum, n_nodes);
    scatter_kernel<<<(nnz + 255) / 256, 256>>>(ev, es, ed, cur, epack, nnz);

    // --- 3 propagation layers ---
    __half* curx = xh;
    __half* nxt  = yh;
    for (int l = 0; l < 3; l++) {
        long long t = (long long)n_nodes * 32;
        int blocks = (int)((t + 255) / 256);
        spmm_csr_kernel<<<blocks, 256>>>(curx, nxt, acc, off, cnt, epack, n_nodes);
        __half* tmp = curx; curx = nxt; nxt = tmp;
    }

    // --- split-precision operand build ---
    {
        int ta = batch * (GK / 2);
        buildA_kernel<<<(ta + 255) / 256, 256>>>(acc, users, Ap, batch);
        int tb = nipad * (GK / 2);
        buildB_kernel<<<(tb + 255) / 256, 256>>>(acc, Bp, nu, ni, nipad);
    }

    // --- HMMA rating GEMM (B-reuse) ---
    cudaFuncSetAttribute(gemm_mma_kernel, cudaFuncAttributeMaxDynamicSharedMemorySize,
                         GEMM_SMEM_TOT);
    int mtiles = (batch + 127) / 128;
    dim3 grid(nipad / 128, (mtiles + MTILES - 1) / MTILES);
    gemm_mma_kernel<<<grid, 256, GEMM_SMEM_TOT>>>(Ap, Bp, (float*)d_out, batch, ni);
}